// round 17
// baseline (speedup 1.0000x reference)
#include <cuda_runtime.h>
#include <cuda_fp16.h>
#include <math.h>
#include <stdint.h>

#define Bsz 128
#define Tlen 1024
#define Iin 256
#define Hd 512
#define Gd 2048      // 4*Hd
#define NBLK 128     // 32 unit-groups x 4 batch-slices
#define NT 256
#define SW0 520      // s_w0 row stride (halves)
#define SWC 1032     // s_wc row stride (halves)
#define SHH 136      // h stage row stride (halves): 128 + 8 pad (17*16B)
#define SMEM_SCAN ((64*SW0 + 64*SWC + 3*32*SHH) * 2)
#define SWX 264      // xgemm smem row stride (halves)
#define SMEM_XG ((64*SWX + 2*32*SWX) * 2)

// ---------------- scratch (static device memory; no allocations) ----------------
static __device__ __align__(16) __half g_xh  [(size_t)Bsz * Tlen * Iin];  // x fp16 [b][t][i]
static __device__ __align__(16) float  g_xg [(size_t)Tlen * Gd  * Bsz];   // [t][g][b]
static __device__ __align__(16) __half g_Wih0h[(size_t)Gd * Iin];         // Wih0 fp16
static __device__ __align__(16) __half g_Wh0h[(size_t)Gd * Hd];           // Whh0 fp16
static __device__ __align__(16) __half g_Wcath[(size_t)Gd * 2 * Hd];      // [Wih1|Whh1] fp16
static __device__ float g_bias0[Gd];
static __device__ float g_bias1[Gd];
static __device__ __align__(16) __half g_h0h[2][(size_t)Bsz * Hd];        // h0[b][unit] fp16
static __device__ __align__(16) __half g_h1h[2][(size_t)Bsz * Hd];        // h1[b][unit] fp16
static __device__ unsigned g_cnt[4 * 32];   // per-slice barrier counters (128B apart)

__device__ __forceinline__ float sigf(float x) { return 1.0f / (1.0f + __expf(-x)); }
__device__ __forceinline__ float tanhfast(float x) {
    float e = __expf(-2.0f * x);
    return (1.0f - e) / (1.0f + e);
}

#define CP16(dst, src)                                                         \
    asm volatile("cp.async.cg.shared.global [%0], [%1], 16;\n"                 \
                 :: "r"(dst), "l"(src) : "memory")

__device__ __forceinline__ unsigned su32(const void* p) {
    return (unsigned)__cvta_generic_to_shared(p);
}

#define LDSM4(r0, r1, r2, r3, addr)                                            \
    asm volatile("ldmatrix.sync.aligned.m8n8.x4.shared.b16 {%0,%1,%2,%3}, [%4];" \
                 : "=r"(r0), "=r"(r1), "=r"(r2), "=r"(r3) : "r"(addr))

#define MMA168(d, a0, a1, a2, a3, b0, b1)                                      \
    asm volatile("mma.sync.aligned.m16n8k16.row.col.f32.f16.f16.f32 "          \
                 "{%0,%1,%2,%3}, {%4,%5,%6,%7}, {%8,%9}, {%0,%1,%2,%3};"       \
                 : "+f"(d[0]), "+f"(d[1]), "+f"(d[2]), "+f"(d[3])              \
                 : "r"(a0), "r"(a1), "r"(a2), "r"(a3), "r"(b0), "r"(b1))

// ---------------- setup ----------------
__global__ void k_prep(const float* __restrict__ bih0, const float* __restrict__ bhh0,
                       const float* __restrict__ bih1, const float* __restrict__ bhh1,
                       const float* __restrict__ Wih1, const float* __restrict__ Whh1,
                       const float* __restrict__ Whh0, const float* __restrict__ Wih0) {
    int i = blockIdx.x * blockDim.x + threadIdx.x;
    if (i < Gd * 2 * Hd) {
        int g = i >> 10;
        int k = i & 1023;
        float v = (k < Hd) ? Wih1[(size_t)g * Hd + k] : Whh1[(size_t)g * Hd + (k - Hd)];
        g_Wcath[i] = __float2half(v);
    }
    if (i < Gd * Hd) g_Wh0h[i] = __float2half(Whh0[i]);
    if (i < Gd * Iin) g_Wih0h[i] = __float2half(Wih0[i]);
    if (i < Gd) { g_bias0[i] = bih0[i] + bhh0[i]; g_bias1[i] = bih1[i] + bhh1[i]; }
    if (i < Bsz * Hd) {
        __half z = __float2half(0.0f);
        g_h0h[0][i] = z; g_h0h[1][i] = z;
        g_h1h[0][i] = z; g_h1h[1][i] = z;
    }
    if (i < 4 * 32) g_cnt[i] = 0u;
}

// ---------------- x -> fp16 ----------------
__global__ void k_xh(const float* __restrict__ x) {
    size_t gid = (size_t)blockIdx.x * blockDim.x + threadIdx.x;
    const float4* src = (const float4*)x + gid * 2;
    float4 v0 = src[0], v1 = src[1];
    __half2 h0 = __floats2half2_rn(v0.x, v0.y);
    __half2 h1 = __floats2half2_rn(v0.z, v0.w);
    __half2 h2 = __floats2half2_rn(v1.x, v1.y);
    __half2 h3 = __floats2half2_rn(v1.z, v1.w);
    uint4 u;
    u.x = *(unsigned*)&h0; u.y = *(unsigned*)&h1;
    u.z = *(unsigned*)&h2; u.w = *(unsigned*)&h3;
    ((uint4*)g_xh)[gid] = u;
}

// ---------------- input GEMM (fp16 tensor cores): xg[t][g][b] = W@x + bias0 ----
// 2-deep x-tile pipeline: chunks t and t+1 outstanding; wait_group 1 hides L2/DRAM.
__global__ void __launch_bounds__(NT) k_xgemm() {
    extern __shared__ __align__(16) unsigned char smem_raw[];
    __half* s_w = (__half*)smem_raw;             // [64][SWX]
    __half* s_x = s_w + 64 * SWX;                // [2][32][SWX]

    const int m = threadIdx.x;
    const int lane = m & 31, w = m >> 5;
    const int gq = lane >> 2, tq = lane & 3;
    const int mi = w & 3, nh = w >> 2;
    const int tt = lane >> 3, tr = lane & 7;

    const int ju = blockIdx.x >> 2, bu = blockIdx.x & 3;
    const int j0 = ju * 16, b0 = bu * 32;

    const int aRow = mi * 16 + (tt & 1) * 8 + tr;
    const int aK   = (tt >> 1) * 8;
    const int bRow = nh * 16 + (tt >> 1) * 8 + tr;
    const int bK   = (tt & 1) * 8;

    const uint32_t suW = su32(s_w), suX = su32(s_x);
    const uint32_t aBase = suW + (uint32_t)(aRow * SWX + aK) * 2;
    const uint32_t bBase = suX + (uint32_t)(bRow * SWX + bK) * 2;

    const int xRow = m >> 3;
    const int xSeg = m & 7;

    for (int idx = m; idx < 2048; idx += NT) {
        int r = idx >> 5, sg = idx & 31;
        int grow = ((r >> 4) << 9) + j0 + (r & 15);
        CP16(suW + (uint32_t)(r * SWX + sg * 8) * 2,
             g_Wih0h + (size_t)grow * Iin + sg * 8);
    }
    asm volatile("cp.async.commit_group;\n" ::: "memory");

    auto issueX = [&](int t) {
        int buf = t & 1;
#pragma unroll
        for (int ss = 0; ss < 4; ++ss) {
            int seg = xSeg + ss * 8;
            CP16(suX + (uint32_t)((buf * 32 + xRow) * SWX + seg * 8) * 2,
                 g_xh + ((size_t)(b0 + xRow) * Tlen + t) * Iin + seg * 8);
        }
        asm volatile("cp.async.commit_group;\n" ::: "memory");
    };
    issueX(0);
    issueX(1);

    const int r1 = (mi << 9) + j0 + gq;
    const int r2 = r1 + 8;
    const float bv1 = g_bias0[r1];
    const float bv2 = g_bias0[r2];

    for (int t = 0; t < Tlen; ++t) {
        if (t + 1 < Tlen) { asm volatile("cp.async.wait_group 1;\n" ::: "memory"); }
        else              { asm volatile("cp.async.wait_group 0;\n" ::: "memory"); }
        __syncthreads();

        float acc[2][4];
#pragma unroll
        for (int nt = 0; nt < 2; ++nt) {
            acc[nt][0] = bv1; acc[nt][1] = bv1;
            acc[nt][2] = bv2; acc[nt][3] = bv2;
        }
        const uint32_t bA = bBase + (uint32_t)((t & 1) * 32 * SWX) * 2;
#pragma unroll
        for (int ks = 0; ks < Iin / 16; ++ks) {
            uint32_t a0, a1, a2, a3, b0r, b1r, b2r, b3r;
            LDSM4(a0, a1, a2, a3, aBase + ks * 32);
            LDSM4(b0r, b1r, b2r, b3r, bA + ks * 32);
            MMA168(acc[0], a0, a1, a2, a3, b0r, b1r);
            MMA168(acc[1], a0, a1, a2, a3, b2r, b3r);
        }
        float* xgt = g_xg + (size_t)t * Gd * Bsz;
#pragma unroll
        for (int nt = 0; nt < 2; ++nt) {
            int col = b0 + nh * 16 + nt * 8 + 2 * tq;
            *(float2*)(xgt + (size_t)r1 * Bsz + col) = make_float2(acc[nt][0], acc[nt][1]);
            *(float2*)(xgt + (size_t)r2 * Bsz + col) = make_float2(acc[nt][2], acc[nt][3]);
        }
        __syncthreads();
        if (t + 2 < Tlen) issueX(t + 2);   // refill buffer consumed this iteration
    }
}

// ---------------- per-slice grid barrier (release-atomic + acquire poll) -------
__device__ __forceinline__ void gridbar(int bu, unsigned expected) {
    __syncthreads();                    // all CTA stores happen-before the release
    if (threadIdx.x == 0) {
        asm volatile("red.release.gpu.global.add.u32 [%0], %1;"
                     :: "l"(&g_cnt[bu * 32]), "r"(1u) : "memory");
        unsigned v;
        do {
            asm volatile("ld.acquire.gpu.u32 %0, [%1];"
                         : "=r"(v) : "l"(&g_cnt[bu * 32]) : "memory");
        } while (v < expected);
    }
    __syncthreads();
}

// ---------------- persistent fp16 tensor-core scan, m32n16 role-split warps ----
// 128 blocks x 256 threads. Warps 0-3: Whh0 (chunks 0-3); during idle chunks 4-7
// they PREFETCH xg[t+2] fragments into registers, so next step's acc-init is a
// register copy (no DRAM latency after the barrier). Warps 4-7: Wcat (chunks 0-7).
// KC=128 halves, 3-stage cp.async h pipeline; s_g aliased into dead stages 0 & 2.
__global__ void __launch_bounds__(NT) k_scan(const float* __restrict__ fcw,
                                             const float* __restrict__ fcb,
                                             float* __restrict__ out) {
    extern __shared__ __align__(16) unsigned char smem_raw[];
    __half* s_w0 = (__half*)smem_raw;                 // [64][SW0]
    __half* s_wc = s_w0 + 64 * SW0;                   // [64][SWC]
    __half* s_h  = s_wc + 64 * SWC;                   // [3][32][SHH]
    float*  s_gA = (float*)s_h;                       // union: stage 0 (64x32 sw)
    float*  s_gB = (float*)(s_h + 2 * 32 * SHH);      // union: stage 2 (64x32 sw)

    const int m = threadIdx.x;
    const int lane = m & 31, w = m >> 5;
    const int gq = lane >> 2, tq = lane & 3;
    const int tt = lane >> 3, tr = lane & 7;

    const bool isW0 = (w < 4);
    const int sub = isW0 ? w : (w - 4);
    const int rb = sub >> 1;                          // row block (rows rb*32..+31)
    const int nh = sub & 1;                           // batch half

    const int ju = blockIdx.x >> 2, bu = blockIdx.x & 3;
    const int j0 = ju * 16, b0 = bu * 32;

    // A fragment bases: two m16 tiles (rb*32, rb*32+16)
    const int aR = rb * 32 + (tt & 1) * 8 + tr;
    const int aK = (tt >> 1) * 8;
    const int wStride = isW0 ? SW0 : SWC;
    const uint32_t suW0 = su32(s_w0), suWc = su32(s_wc), suH = su32(s_h);
    const uint32_t aBase0 = (isW0 ? suW0 : suWc) + (uint32_t)(aR * wStride + aK) * 2;
    const uint32_t aBase1 = aBase0 + (uint32_t)(16 * wStride) * 2;
    const int bR = nh * 16 + (tt >> 1) * 8 + tr;
    const int bK = (tt & 1) * 8;
    const uint32_t bBase = suH + (uint32_t)(bR * SHH + bK) * 2;

    const int dRow = m >> 3, seg = m & 7;             // staging duties (2 CP16/chunk)
    const int bb = m >> 3, up = m & 7;                // activation mapping

    // gate rows owned by this warp: grow(a,o) for fragment rows rb*32+16a+gq+o
    const int grow00 = ((2 * rb + 0) << 9) + j0 + gq;   // a=0, o=0
    const int grow01 = grow00 + 8;                      // a=0, o=8
    const int grow10 = ((2 * rb + 1) << 9) + j0 + gq;   // a=1
    const int grow11 = grow10 + 8;

    // ===== resident weight slices =====
    for (int idx = m; idx < 4096; idx += NT) {
        int r = idx >> 6, sg = idx & 63;
        int grow = ((r >> 4) << 9) + j0 + (r & 15);
        CP16(suW0 + (uint32_t)(r * SW0 + sg * 8) * 2,
             g_Wh0h + (size_t)grow * Hd + sg * 8);
    }
    for (int idx = m; idx < 8192; idx += NT) {
        int r = idx >> 7, sg = idx & 127;
        int grow = ((r >> 4) << 9) + j0 + (r & 15);
        CP16(suWc + (uint32_t)(r * SWC + sg * 8) * 2,
             g_Wcath + (size_t)grow * (2 * Hd) + sg * 8);
    }
    asm volatile("cp.async.commit_group;\n" ::: "memory");
    asm volatile("cp.async.wait_group 0;\n" ::: "memory");
    __syncthreads();

    float c0a = 0.f, c0b = 0.f, c1a = 0.f, c1b = 0.f;
    unsigned bar = 0;
    float xgf[16];                       // light warps: prefetched xg fragments

    // xg fragment load helper (light warps)
    auto load_xgf = [&](int tP) {
        const float* xgt = g_xg + (size_t)tP * Gd * Bsz;
#pragma unroll
        for (int nt = 0; nt < 2; ++nt) {
            int col = b0 + nh * 16 + nt * 8 + 2 * tq;
            float2 v;
            v = *(const float2*)(xgt + (size_t)grow00 * Bsz + col);
            xgf[nt * 8 + 0] = v.x; xgf[nt * 8 + 1] = v.y;
            v = *(const float2*)(xgt + (size_t)grow01 * Bsz + col);
            xgf[nt * 8 + 2] = v.x; xgf[nt * 8 + 3] = v.y;
            v = *(const float2*)(xgt + (size_t)grow10 * Bsz + col);
            xgf[nt * 8 + 4] = v.x; xgf[nt * 8 + 5] = v.y;
            v = *(const float2*)(xgt + (size_t)grow11 * Bsz + col);
            xgf[nt * 8 + 6] = v.x; xgf[nt * 8 + 7] = v.y;
        }
    };

    // ===== prologue A(0) =====
    {
        const float* xg0 = g_xg;
        float gi = xg0[((size_t)(0 * Hd) + j0 + up) * Bsz + b0 + bb];
        float gg = xg0[((size_t)(2 * Hd) + j0 + up) * Bsz + b0 + bb];
        float go = xg0[((size_t)(3 * Hd) + j0 + up) * Bsz + b0 + bb];
        c0a = sigf(gi) * tanhfast(gg);
        g_h0h[0][(size_t)(b0 + bb) * Hd + j0 + up] = __float2half(sigf(go) * tanhfast(c0a));
        gi = xg0[((size_t)(0 * Hd) + j0 + up + 8) * Bsz + b0 + bb];
        gg = xg0[((size_t)(2 * Hd) + j0 + up + 8) * Bsz + b0 + bb];
        go = xg0[((size_t)(3 * Hd) + j0 + up + 8) * Bsz + b0 + bb];
        c0b = sigf(gi) * tanhfast(gg);
        g_h0h[0][(size_t)(b0 + bb) * Hd + j0 + up + 8] = __float2half(sigf(go) * tanhfast(c0b));
    }
    if (isW0) load_xgf(1);               // xg for step 0's A(1)
    gridbar(bu, ++bar * 32);

    const float bv00 = __ldg(&g_bias1[grow00]);
    const float bv01 = __ldg(&g_bias1[grow01]);
    const float bv10 = __ldg(&g_bias1[grow10]);
    const float bv11 = __ldg(&g_bias1[grow11]);

    for (int t = 0; t < Tlen; ++t) {
        const __half* h0cur = g_h0h[t & 1];          // h0(t)
        const __half* h1prv = g_h1h[(t + 1) & 1];    // h1(t-1)
        __half*       h1nxt = g_h1h[t & 1];          // h1(t)
        __half*       h0nxt = g_h0h[(t + 1) & 1];    // h0(t+1)

        float acc[2][2][4];                          // [mtile a][n8 b][frag]
        if (isW0) {
            // acc init = prefetched xg[t+1] fragments (register copy)
#pragma unroll
            for (int nt = 0; nt < 2; ++nt) {
                acc[0][nt][0] = xgf[nt * 8 + 0]; acc[0][nt][1] = xgf[nt * 8 + 1];
                acc[0][nt][2] = xgf[nt * 8 + 2]; acc[0][nt][3] = xgf[nt * 8 + 3];
                acc[1][nt][0] = xgf[nt * 8 + 4]; acc[1][nt][1] = xgf[nt * 8 + 5];
                acc[1][nt][2] = xgf[nt * 8 + 6]; acc[1][nt][3] = xgf[nt * 8 + 7];
            }
        } else {
#pragma unroll
            for (int nt = 0; nt < 2; ++nt) {
                acc[0][nt][0] = bv00; acc[0][nt][1] = bv00;
                acc[0][nt][2] = bv01; acc[0][nt][3] = bv01;
                acc[1][nt][0] = bv10; acc[1][nt][1] = bv10;
                acc[1][nt][2] = bv11; acc[1][nt][3] = bv11;
            }
        }

        auto issue = [&](int c) {
            int st = c % 3;
            const __half* src = (c < 4) ? (h0cur + c * 128) : (h1prv + (c - 4) * 128);
            uint32_t dst = suH + (uint32_t)((st * 32 + dRow) * SHH + seg * 8) * 2;
            const __half* gsrc = src + (size_t)(b0 + dRow) * Hd + seg * 8;
            CP16(dst, gsrc);
            CP16(dst + 128, gsrc + 64);
            asm volatile("cp.async.commit_group;\n" ::: "memory");
        };

        issue(0); issue(1);
#pragma unroll 1
        for (int c = 0; c < 8; ++c) {
            if (c < 7) { asm volatile("cp.async.wait_group 1;\n" ::: "memory"); }
            else       { asm volatile("cp.async.wait_group 0;\n" ::: "memory"); }
            __syncthreads();
            if (c + 2 < 8) issue(c + 2);
            if (isW0 && c >= 4) {
                if (c == 4) load_xgf((t + 2 < Tlen) ? (t + 2) : (Tlen - 1));
                continue;
            }
            const uint32_t bA = bBase + (uint32_t)((c % 3) * 32 * SHH) * 2;
            const uint32_t aOff = (uint32_t)(c * 128) * 2;
#pragma unroll
            for (int ks = 0; ks < 8; ++ks) {
                uint32_t a0, a1, a2, a3, a4, a5, a6, a7, b0r, b1r, b2r, b3r;
                LDSM4(b0r, b1r, b2r, b3r, bA + ks * 32);
                LDSM4(a0, a1, a2, a3, aBase0 + aOff + ks * 32);
                LDSM4(a4, a5, a6, a7, aBase1 + aOff + ks * 32);
                MMA168(acc[0][0], a0, a1, a2, a3, b0r, b1r);
                MMA168(acc[0][1], a0, a1, a2, a3, b2r, b3r);
                MMA168(acc[1][0], a4, a5, a6, a7, b0r, b1r);
                MMA168(acc[1][1], a4, a5, a6, a7, b2r, b3r);
            }
        }

        // publish gates (swizzled stride-32): dst row r, col c -> c ^ ((r&7)<<2)
        {
            float* dst = isW0 ? s_gA : s_gB;
#pragma unroll
            for (int a = 0; a < 2; ++a) {
#pragma unroll
                for (int nt = 0; nt < 2; ++nt) {
                    int row0 = rb * 32 + 16 * a + gq;      // row0 & 7 == gq
                    int col  = nh * 16 + nt * 8 + 2 * tq;
                    int sc   = col ^ (gq << 2);
                    *(float2*)&dst[row0 * 32 + sc] = make_float2(acc[a][nt][0], acc[a][nt][1]);
                    *(float2*)&dst[(row0 + 8) * 32 + sc] = make_float2(acc[a][nt][2], acc[a][nt][3]);
                }
            }
        }
        __syncthreads();

        // ===== activations: read swizzled s_g (col bb -> bb ^ (up<<2)) =====
        {
            const int sc = bb ^ (up << 2);
            // B(t) -> h1(t)
            float gi = s_gB[(0 * 16 + up) * 32 + sc];
            float gf = s_gB[(1 * 16 + up) * 32 + sc];
            float gg = s_gB[(2 * 16 + up) * 32 + sc];
            float go = s_gB[(3 * 16 + up) * 32 + sc];
            c1a = sigf(gf) * c1a + sigf(gi) * tanhfast(gg);
            h1nxt[(size_t)(b0 + bb) * Hd + j0 + up] = __float2half(sigf(go) * tanhfast(c1a));
            gi = s_gB[(0 * 16 + up + 8) * 32 + sc];
            gf = s_gB[(1 * 16 + up + 8) * 32 + sc];
            gg = s_gB[(2 * 16 + up + 8) * 32 + sc];
            go = s_gB[(3 * 16 + up + 8) * 32 + sc];
            c1b = sigf(gf) * c1b + sigf(gi) * tanhfast(gg);
            h1nxt[(size_t)(b0 + bb) * Hd + j0 + up + 8] = __float2half(sigf(go) * tanhfast(c1b));
            // A(t+1) -> h0(t+1)  (bogus-but-unused at t=1023)
            gi = s_gA[(0 * 16 + up) * 32 + sc];
            gf = s_gA[(1 * 16 + up) * 32 + sc];
            gg = s_gA[(2 * 16 + up) * 32 + sc];
            go = s_gA[(3 * 16 + up) * 32 + sc];
            c0a = sigf(gf) * c0a + sigf(gi) * tanhfast(gg);
            h0nxt[(size_t)(b0 + bb) * Hd + j0 + up] = __float2half(sigf(go) * tanhfast(c0a));
            gi = s_gA[(0 * 16 + up + 8) * 32 + sc];
            gf = s_gA[(1 * 16 + up + 8) * 32 + sc];
            gg = s_gA[(2 * 16 + up + 8) * 32 + sc];
            go = s_gA[(3 * 16 + up + 8) * 32 + sc];
            c0b = sigf(gf) * c0b + sigf(gi) * tanhfast(gg);
            h0nxt[(size_t)(b0 + bb) * Hd + j0 + up + 8] = __float2half(sigf(go) * tanhfast(c0b));
        }
        gridbar(bu, ++bar * 32);
    }

    // ===== final FC: ju==0 block of each slice handles its 32 batch rows =====
    if (ju == 0 && m < 32) {
        const __half* hf = g_h1h[1] + (size_t)(b0 + m) * Hd;
        float a = __ldg(fcb);
#pragma unroll 8
        for (int j = 0; j < Hd; ++j)
            a += __half2float(__ldcg(&hf[j])) * __ldg(&fcw[j]);
        out[b0 + m] = a;
    }
}

extern "C" void kernel_launch(void* const* d_in, const int* in_sizes, int n_in,
                              void* d_out, int out_size) {
    const float* x    = (const float*)d_in[0];
    const float* Wih0 = (const float*)d_in[1];
    const float* Whh0 = (const float*)d_in[2];
    const float* bih0 = (const float*)d_in[3];
    const float* bhh0 = (const float*)d_in[4];
    const float* Wih1 = (const float*)d_in[5];
    const float* Whh1 = (const float*)d_in[6];
    const float* bih1 = (const float*)d_in[7];
    const float* bhh1 = (const float*)d_in[8];
    const float* fcw  = (const float*)d_in[9];
    const float* fcb  = (const float*)d_in[10];
    float* out = (float*)d_out;

    cudaFuncSetAttribute(k_scan, cudaFuncAttributeMaxDynamicSharedMemorySize, SMEM_SCAN);
    cudaFuncSetAttribute(k_xgemm, cudaFuncAttributeMaxDynamicSharedMemorySize, SMEM_XG);

    k_prep<<<(Gd * 2 * Hd) / 256, 256>>>(bih0, bhh0, bih1, bhh1, Wih1, Whh1, Whh0, Wih0);

    k_xh<<<((size_t)Bsz * Tlen * Iin / 8) / 256, 256>>>(x);

    k_xgemm<<<NBLK, NT, SMEM_XG>>>();

    k_scan<<<NBLK, NT, SMEM_SCAN>>>(fcw, fcb, out);
}